// round 15
// baseline (speedup 1.0000x reference)
#include <cuda_runtime.h>

#define NELEM 589824      // 64*96*96
#define NVEC4 147456      // NELEM/4
#define BATCH 2
#define TOPK  2048
#define CAP   4096
#define NBINS 4096        // top-12-bit key histogram
#define NBLK  148
#define NTHR  512

// ---------------- device scratch ----------------
__device__ unsigned int        g_hist[BATCH][NBINS];   // zeroed at load; selbin stage re-zeroes
__device__ int                 g_cnt[BATCH];           // zeroed at load; selbin stage re-zeroes
__device__ int                 g_bstar[BATCH];
__device__ int                 g_rank[BATCH][CAP];     // zeroed in selbin stage each call
__device__ unsigned long long  g_cand[BATCH][CAP];
__device__ float               g_out7[BATCH][TOPK][7];
__device__ float               g_lo[BATCH][TOPK][3];
__device__ float               g_hi[BATCH][TOPK][3];
__device__ float               g_vol[BATCH][TOPK];
__device__ unsigned long long  g_mask[BATCH][32][TOPK];   // [word][row]; lower triangle untouched
// grid barrier state (gen monotonically increases across calls; count returns to 0)
__device__ unsigned int        g_bar_cnt = 0;
__device__ unsigned int        g_bar_gen = 0;

__device__ __forceinline__ unsigned int fkey(float f) {
    unsigned int b = __float_as_uint(f);
    unsigned int m = ((unsigned int)((int)b >> 31)) | 0x80000000u;
    return b ^ m;
}
__device__ __forceinline__ float fkey_inv(unsigned int u) {
    unsigned int b = (u & 0x80000000u) ? (u ^ 0x80000000u) : ~u;
    return __uint_as_float(b);
}

// software grid barrier (all NBLK blocks co-resident: 148 blocks on >=148 SMs)
__device__ __forceinline__ void gsync() {
    __syncthreads();
    if (threadIdx.x == 0) {
        volatile unsigned int* genp = &g_bar_gen;
        unsigned int my = *genp;
        __threadfence();
        unsigned int ticket = atomicAdd(&g_bar_cnt, 1u);
        if (ticket == NBLK - 1) {
            g_bar_cnt = 0;
            __threadfence();
            atomicAdd(&g_bar_gen, 1u);
        } else {
            while (*genp == my) { }
        }
        __threadfence();
    }
    __syncthreads();
}

__device__ __forceinline__ void hadd(unsigned int* sh, unsigned int bin) {
    unsigned int m = __match_any_sync(0xFFFFFFFFu, bin);
    if ((threadIdx.x & 31) == (unsigned)(__ffs(m) - 1))
        atomicAdd(&sh[bin], (unsigned int)__popc(m));
}

__global__ void __launch_bounds__(NTHR, 1)
k_all(const float* __restrict__ bboxes, const float* __restrict__ scores,
      float* __restrict__ out) {
    __shared__ __align__(16) unsigned char sbuf[18688];
    const int bid = blockIdx.x, t = threadIdx.x;

    // ============ stage 1: histogram (74 blocks per batch) ============
    {
        unsigned int* sh = (unsigned int*)sbuf;
        for (int i = t; i < NBINS; i += NTHR) sh[i] = 0u;
        __syncthreads();
        int b = bid & 1, chunk = bid >> 1;
        const float4* s = (const float4*)(scores + (size_t)b * NELEM);
        for (int i = chunk * NTHR + t; i < NVEC4; i += 74 * NTHR) {
            float4 v = s[i];
            hadd(sh, fkey(v.x) >> 20);
            hadd(sh, fkey(v.y) >> 20);
            hadd(sh, fkey(v.z) >> 20);
            hadd(sh, fkey(v.w) >> 20);
        }
        __syncthreads();
        for (int i = t; i < NBINS; i += NTHR) {
            unsigned int c = sh[i];
            if (c) atomicAdd(&g_hist[b][i], c);
        }
    }
    gsync();

    // ============ stage 2: threshold bin + scratch reset (blocks 0,1) ============
    if (bid < BATCH) {
        int b = bid;
        unsigned int* sbin = (unsigned int*)sbuf;            // 4096
        unsigned int* tsum = (unsigned int*)(sbuf + 16384);  // 512
        uint4 z4 = make_uint4(0u, 0u, 0u, 0u);
        uint4 v0 = ((const uint4*)g_hist[b])[2 * t];
        uint4 v1 = ((const uint4*)g_hist[b])[2 * t + 1];
        ((uint4*)sbin)[2 * t] = v0;
        ((uint4*)sbin)[2 * t + 1] = v1;
        tsum[t] = v0.x + v0.y + v0.z + v0.w + v1.x + v1.y + v1.z + v1.w;
        ((uint4*)g_hist[b])[2 * t] = z4;                     // reset for next call
        ((uint4*)g_hist[b])[2 * t + 1] = z4;
        ((uint4*)g_rank[b])[2 * t] = z4;                     // zero 4096 ranks
        ((uint4*)g_rank[b])[2 * t + 1] = z4;
        if (t == 0) g_cnt[b] = 0;
        __syncthreads();
        if (t < 32) {
            unsigned int s = 0;
            for (int k = 0; k < 16; k++) s += tsum[t * 16 + k];
            unsigned int suf = s;
            for (int d = 1; d < 32; d <<= 1) {
                unsigned int x = __shfl_down_sync(0xFFFFFFFFu, suf, d);
                if (t + d < 32) suf += x;
            }
            unsigned int ball = __ballot_sync(0xFFFFFFFFu, suf >= TOPK);
            int L = 31 - __clz(ball);
            if (t == L) {
                unsigned int c = suf - s;
                int T = L * 16;
                for (int k = 15; k >= 0; k--) {
                    c += tsum[L * 16 + k];
                    if (c >= TOPK) { T = L * 16 + k; break; }
                }
                unsigned int c2 = c - tsum[T];
                int bin = 8 * T;
                for (int q = 7; q >= 0; q--) {
                    c2 += sbin[8 * T + q];
                    if (c2 >= TOPK) { bin = 8 * T + q; break; }
                }
                g_bstar[b] = bin;
            }
        }
    }
    gsync();

    // ============ stage 3: gather candidates ============
    {
        int b = bid & 1, chunk = bid >> 1;
        int thr = g_bstar[b];
        const float4* s = (const float4*)(scores + (size_t)b * NELEM);
        for (int i = chunk * NTHR + t; i < NVEC4; i += 74 * NTHR) {
            float4 v = s[i];
            float vv[4] = {v.x, v.y, v.z, v.w};
#pragma unroll
            for (int c = 0; c < 4; c++) {
                unsigned int u = fkey(vv[c]);
                if ((int)(u >> 20) >= thr) {
                    int pos = atomicAdd(&g_cnt[b], 1);
                    if (pos < CAP) {
                        unsigned int p = (unsigned int)(4 * i + c);
                        g_cand[b][pos] = ((unsigned long long)u << 32) | (~p);
                    }
                }
            }
        }
    }
    gsync();

    // ============ stage 4: tiled rank (512x512 tiles, 128 jobs) ============
    if (bid < 128) {
        int b = bid >> 6, r = bid & 63, ct = r >> 3, jt = r & 7;
        int cnt = __ldcg(&g_cnt[b]); if (cnt > CAP) cnt = CAP;
        unsigned long long* tile = (unsigned long long*)sbuf;   // 512*8 = 4KB
        int c = ct * 512 + t;
        unsigned long long ki = (c < cnt) ? g_cand[b][c] : 0ULL;
        int j = jt * 512 + t;
        tile[t] = (j < cnt) ? g_cand[b][j] : 0ULL;
        __syncthreads();
        if (c < cnt) {
            int rk = 0;
#pragma unroll 16
            for (int jj = 0; jj < 512; jj++)
                rk += (tile[jj] > ki);
            if (rk) atomicAdd(&g_rank[b][c], rk);
        }
    }
    gsync();

    // ============ stage 5: scatter + deparametrize (8192 candidates) ============
    {
        int gid = bid * NTHR + t;
        if (gid < BATCH * CAP) {
            int b = gid >> 12, c = gid & (CAP - 1);
            int cnt = __ldcg(&g_cnt[b]); if (cnt > CAP) cnt = CAP;
            if (c < cnt) {
                unsigned long long ki = g_cand[b][c];
                int row = __ldcg(&g_rank[b][c]);
                if (row < TOPK) {
                    unsigned int idx = ~(unsigned int)(ki & 0xFFFFFFFFu);
                    int d = idx / 9216;
                    int rem = idx - d * 9216;
                    int h = rem / 96;
                    int w = rem - h * 96;
                    float coord[3] = { (float)d + 0.5f, (float)h + 0.5f, (float)w + 0.5f };
                    const float* bb = bboxes + (size_t)b * 6 * NELEM + idx;
                    g_out7[b][row][0] = fkey_inv((unsigned int)(ki >> 32));
                    float vol = 1.0f;
#pragma unroll
                    for (int q = 0; q < 3; q++) {
                        float ctr = bb[(size_t)q * NELEM] * 12.0f + coord[q];
                        float sz  = expf(bb[(size_t)(q + 3) * NELEM]) * 12.0f;
                        g_out7[b][row][1 + q] = ctr;
                        g_out7[b][row][4 + q] = sz;
                        float half = sz * 0.5f;
                        g_lo[b][row][q] = ctr - half;
                        g_hi[b][row][q] = ctr + half;
                        vol *= sz;
                    }
                    g_vol[b][row] = vol;
                }
            }
        }
    }
    gsync();

    // ============ stage 6: IoU bitmask, upper triangle (1056 jobs of 64 threads) ====
    {
        int g = t >> 6, l64 = t & 63;
        int slot = bid * 8 + g;
        bool act = slot < 1056;
        int b = 0, itile = 0, jw = 0;
        if (act) {
            b = slot / 528;
            int r = slot - b * 528;
            int it = 0;
            while (r >= 32 - it) { r -= 32 - it; it++; }
            itile = it; jw = it + r;
        }
        float* sj = (float*)sbuf + g * 448;     // 64 boxes * 7 floats per group
        if (act) {
            int j = jw * 64 + l64;
            sj[l64 * 7 + 0] = g_lo[b][j][0];
            sj[l64 * 7 + 1] = g_lo[b][j][1];
            sj[l64 * 7 + 2] = g_lo[b][j][2];
            sj[l64 * 7 + 3] = g_hi[b][j][0];
            sj[l64 * 7 + 4] = g_hi[b][j][1];
            sj[l64 * 7 + 5] = g_hi[b][j][2];
            sj[l64 * 7 + 6] = g_vol[b][j];
        }
        __syncthreads();
        if (act) {
            int i = itile * 64 + l64;
            float lo0 = g_lo[b][i][0], lo1 = g_lo[b][i][1], lo2 = g_lo[b][i][2];
            float hi0 = g_hi[b][i][0], hi1 = g_hi[b][i][1], hi2 = g_hi[b][i][2];
            float voli = g_vol[b][i];
            int j0 = jw * 64;
            unsigned long long bits = 0ULL;
#pragma unroll 8
            for (int jj = 0; jj < 64; jj++) {
                int j = j0 + jj;
                const float* p = sj + jj * 7;
                float t0 = fmaxf(fminf(hi0, p[3]) - fmaxf(lo0, p[0]), 0.0f);
                float t1 = fmaxf(fminf(hi1, p[4]) - fmaxf(lo1, p[1]), 0.0f);
                float t2 = fmaxf(fminf(hi2, p[5]) - fmaxf(lo2, p[2]), 0.0f);
                float inter = t0 * t1 * t2;
                float uni = voli + p[6] - inter;
                float q = 0.25f * uni;              // exactly representable scale
                bool sup = false;
                if (inter > q) {
                    if (inter < q * 1.000001f) sup = (inter / uni > 0.25f);
                    else                       sup = true;
                }
                if (sup && (j > i)) bits |= (1ULL << jj);
            }
            g_mask[b][jw][i] = bits;
        }
    }
    gsync();

    // ============ stage 7: sparse greedy reduce (1 warp) + fused output ============
    if (bid < BATCH) {
        int b = bid;
        unsigned long long (*sdiag)[64] = (unsigned long long (*)[64])sbuf;  // 16KB
        unsigned long long* skeep = (unsigned long long*)(sbuf + 16384);
        for (int e = t; e < 2048; e += NTHR) {
            int w = e >> 6, r = e & 63;
            sdiag[w][r] = __ldcg(&g_mask[b][w][w * 64 + r]);
        }
        __syncthreads();
        if (t < 32) {
            int lane = t;
            unsigned long long remv = 0ULL;
            for (int w = 0; w < 32; w++) {
                unsigned long long kept = 0ULL;
                if (lane == w) {
                    // greedy over alive bits only (~few kept per word)
                    unsigned long long a = ~remv;
                    while (a) {
                        int bit = __ffsll(a) - 1;
                        kept |= 1ULL << bit;
                        a &= ~(sdiag[w][bit] | (1ULL << bit));
                    }
                    // every alive bit ended kept or suppressed within this word
                    remv |= ~kept;
                }
                kept = __shfl_sync(0xFFFFFFFFu, kept, w);   // one shfl per word
                if (lane > w) {
                    // OR columns of kept rows only (independent loads, MLP at L2)
                    const unsigned long long* col = &g_mask[b][lane][w * 64];
                    unsigned long long k = kept, rm = 0ULL;
                    while (k) {
                        int q = __ffsll(k) - 1;
                        k &= k - 1;
                        rm |= __ldcg(&col[q]);
                    }
                    remv |= rm;
                }
            }
            skeep[lane] = ~remv;
        }
        __syncthreads();
        for (int row = t; row < TOPK; row += NTHR) {
            bool keep = (skeep[row >> 6] >> (row & 63)) & 1ULL;
            float* o = out + ((size_t)b * TOPK + row) * 7;
#pragma unroll
            for (int c = 0; c < 7; c++) o[c] = keep ? g_out7[b][row][c] : 0.0f;
        }
    }
}

extern "C" void kernel_launch(void* const* d_in, const int* in_sizes, int n_in,
                              void* d_out, int out_size) {
    const float* bboxes = (const float*)d_in[0];   // (2,6,64,96,96)
    const float* scores = (const float*)d_in[1];   // (2,64,96,96)
    float* out = (float*)d_out;                    // (2,2048,7)
    k_all<<<NBLK, NTHR>>>(bboxes, scores, out);
}

// round 17
// speedup vs baseline: 8.2173x; 8.2173x over previous
#include <cuda_runtime.h>

#define NELEM 589824      // 64*96*96
#define NVEC4 147456      // NELEM/4
#define BATCH 2
#define TOPK  2048
#define CAP   4096
#define NBINS 4096        // top-12-bit key histogram
#define NBLK  148
#define NTHR  512
#define CHUNK 16

// ---------------- device scratch ----------------
__device__ unsigned int        g_hist[BATCH][NBINS];   // zeroed at load; selbin stage re-zeroes
__device__ int                 g_cnt[BATCH];           // zeroed at load; selbin stage re-zeroes
__device__ int                 g_bstar[BATCH];
__device__ int                 g_rank[BATCH][CAP];     // zeroed in selbin stage each call
__device__ unsigned long long  g_cand[BATCH][CAP];
__device__ float               g_out7[BATCH][TOPK][7];
__device__ float               g_lo[BATCH][TOPK][3];
__device__ float               g_hi[BATCH][TOPK][3];
__device__ float               g_vol[BATCH][TOPK];
__device__ unsigned long long  g_mask[BATCH][32][TOPK];   // [word][row]; lower triangle untouched
__device__ unsigned long long  g_nz[BATCH][32];           // rows with nonzero mask row
// grid barrier state (gen monotonically increases across calls; count returns to 0)
__device__ unsigned int        g_bar_cnt = 0;
__device__ unsigned int        g_bar_gen = 0;

__device__ __forceinline__ unsigned int fkey(float f) {
    unsigned int b = __float_as_uint(f);
    unsigned int m = ((unsigned int)((int)b >> 31)) | 0x80000000u;
    return b ^ m;
}
__device__ __forceinline__ float fkey_inv(unsigned int u) {
    unsigned int b = (u & 0x80000000u) ? (u ^ 0x80000000u) : ~u;
    return __uint_as_float(b);
}

// software grid barrier (all NBLK blocks co-resident: 148 blocks on >=148 SMs)
__device__ __forceinline__ void gsync() {
    __syncthreads();
    if (threadIdx.x == 0) {
        volatile unsigned int* genp = &g_bar_gen;
        unsigned int my = *genp;
        __threadfence();
        unsigned int ticket = atomicAdd(&g_bar_cnt, 1u);
        if (ticket == NBLK - 1) {
            g_bar_cnt = 0;
            __threadfence();
            atomicAdd(&g_bar_gen, 1u);
        } else {
            while (*genp == my) { }
        }
        __threadfence();
    }
    __syncthreads();
}

__device__ __forceinline__ void hadd(unsigned int* sh, unsigned int bin) {
    unsigned int m = __match_any_sync(0xFFFFFFFFu, bin);
    if ((threadIdx.x & 31) == (unsigned)(__ffs(m) - 1))
        atomicAdd(&sh[bin], (unsigned int)__popc(m));
}

__global__ void __launch_bounds__(NTHR, 1)
k_all(const float* __restrict__ bboxes, const float* __restrict__ scores,
      float* __restrict__ out) {
    __shared__ __align__(16) unsigned char sbuf[18688];
    const int bid = blockIdx.x, t = threadIdx.x;

    // ============ stage 1: histogram (74 blocks per batch) ============
    {
        unsigned int* sh = (unsigned int*)sbuf;
        for (int i = t; i < NBINS; i += NTHR) sh[i] = 0u;
        __syncthreads();
        int b = bid & 1, chunk = bid >> 1;
        const float4* s = (const float4*)(scores + (size_t)b * NELEM);
        for (int i = chunk * NTHR + t; i < NVEC4; i += 74 * NTHR) {
            float4 v = s[i];
            hadd(sh, fkey(v.x) >> 20);
            hadd(sh, fkey(v.y) >> 20);
            hadd(sh, fkey(v.z) >> 20);
            hadd(sh, fkey(v.w) >> 20);
        }
        __syncthreads();
        for (int i = t; i < NBINS; i += NTHR) {
            unsigned int c = sh[i];
            if (c) atomicAdd(&g_hist[b][i], c);
        }
    }
    gsync();

    // ============ stage 2: threshold bin + scratch reset (blocks 0,1) ============
    if (bid < BATCH) {
        int b = bid;
        unsigned int* sbin = (unsigned int*)sbuf;            // 4096
        unsigned int* tsum = (unsigned int*)(sbuf + 16384);  // 512
        uint4 z4 = make_uint4(0u, 0u, 0u, 0u);
        uint4 v0 = ((const uint4*)g_hist[b])[2 * t];
        uint4 v1 = ((const uint4*)g_hist[b])[2 * t + 1];
        ((uint4*)sbin)[2 * t] = v0;
        ((uint4*)sbin)[2 * t + 1] = v1;
        tsum[t] = v0.x + v0.y + v0.z + v0.w + v1.x + v1.y + v1.z + v1.w;
        ((uint4*)g_hist[b])[2 * t] = z4;                     // reset for next call
        ((uint4*)g_hist[b])[2 * t + 1] = z4;
        ((uint4*)g_rank[b])[2 * t] = z4;                     // zero 4096 ranks
        ((uint4*)g_rank[b])[2 * t + 1] = z4;
        if (t == 0) g_cnt[b] = 0;
        if (t < 32) g_nz[b][t] = 0ULL;                       // reset nz bitmap
        __syncthreads();
        if (t < 32) {
            unsigned int s = 0;
            for (int k = 0; k < 16; k++) s += tsum[t * 16 + k];
            unsigned int suf = s;
            for (int d = 1; d < 32; d <<= 1) {
                unsigned int x = __shfl_down_sync(0xFFFFFFFFu, suf, d);
                if (t + d < 32) suf += x;
            }
            unsigned int ball = __ballot_sync(0xFFFFFFFFu, suf >= TOPK);
            int L = 31 - __clz(ball);
            if (t == L) {
                unsigned int c = suf - s;
                int T = L * 16;
                for (int k = 15; k >= 0; k--) {
                    c += tsum[L * 16 + k];
                    if (c >= TOPK) { T = L * 16 + k; break; }
                }
                unsigned int c2 = c - tsum[T];
                int bin = 8 * T;
                for (int q = 7; q >= 0; q--) {
                    c2 += sbin[8 * T + q];
                    if (c2 >= TOPK) { bin = 8 * T + q; break; }
                }
                g_bstar[b] = bin;
            }
        }
    }
    gsync();

    // ============ stage 3: gather candidates ============
    {
        int b = bid & 1, chunk = bid >> 1;
        int thr = g_bstar[b];
        const float4* s = (const float4*)(scores + (size_t)b * NELEM);
        for (int i = chunk * NTHR + t; i < NVEC4; i += 74 * NTHR) {
            float4 v = s[i];
            float vv[4] = {v.x, v.y, v.z, v.w};
#pragma unroll
            for (int c = 0; c < 4; c++) {
                unsigned int u = fkey(vv[c]);
                if ((int)(u >> 20) >= thr) {
                    int pos = atomicAdd(&g_cnt[b], 1);
                    if (pos < CAP) {
                        unsigned int p = (unsigned int)(4 * i + c);
                        g_cand[b][pos] = ((unsigned long long)u << 32) | (~p);
                    }
                }
            }
        }
    }
    gsync();

    // ============ stage 4: tiled rank (512x512 tiles, 128 jobs) ============
    if (bid < 128) {
        int b = bid >> 6, r = bid & 63, ct = r >> 3, jt = r & 7;
        int cnt = __ldcg(&g_cnt[b]); if (cnt > CAP) cnt = CAP;
        unsigned long long* tile = (unsigned long long*)sbuf;   // 512*8 = 4KB
        int c = ct * 512 + t;
        unsigned long long ki = (c < cnt) ? g_cand[b][c] : 0ULL;
        int j = jt * 512 + t;
        tile[t] = (j < cnt) ? g_cand[b][j] : 0ULL;
        __syncthreads();
        if (c < cnt) {
            int rk = 0;
#pragma unroll 16
            for (int jj = 0; jj < 512; jj++)
                rk += (tile[jj] > ki);
            if (rk) atomicAdd(&g_rank[b][c], rk);
        }
    }
    gsync();

    // ============ stage 5: scatter + deparametrize (8192 candidates) ============
    {
        int gid = bid * NTHR + t;
        if (gid < BATCH * CAP) {
            int b = gid >> 12, c = gid & (CAP - 1);
            int cnt = __ldcg(&g_cnt[b]); if (cnt > CAP) cnt = CAP;
            if (c < cnt) {
                unsigned long long ki = g_cand[b][c];
                int row = __ldcg(&g_rank[b][c]);
                if (row < TOPK) {
                    unsigned int idx = ~(unsigned int)(ki & 0xFFFFFFFFu);
                    int d = idx / 9216;
                    int rem = idx - d * 9216;
                    int h = rem / 96;
                    int w = rem - h * 96;
                    float coord[3] = { (float)d + 0.5f, (float)h + 0.5f, (float)w + 0.5f };
                    const float* bb = bboxes + (size_t)b * 6 * NELEM + idx;
                    g_out7[b][row][0] = fkey_inv((unsigned int)(ki >> 32));
                    float vol = 1.0f;
#pragma unroll
                    for (int q = 0; q < 3; q++) {
                        float ctr = bb[(size_t)q * NELEM] * 12.0f + coord[q];
                        float sz  = expf(bb[(size_t)(q + 3) * NELEM]) * 12.0f;
                        g_out7[b][row][1 + q] = ctr;
                        g_out7[b][row][4 + q] = sz;
                        float half = sz * 0.5f;
                        g_lo[b][row][q] = ctr - half;
                        g_hi[b][row][q] = ctr + half;
                        vol *= sz;
                    }
                    g_vol[b][row] = vol;
                }
            }
        }
    }
    gsync();

    // ============ stage 6: IoU bitmask + nz bitmap (1056 jobs of 64 threads) ====
    {
        int g = t >> 6, l64 = t & 63;
        int slot = bid * 8 + g;
        bool act = slot < 1056;
        int b = 0, itile = 0, jw = 0;
        if (act) {
            b = slot / 528;
            int r = slot - b * 528;
            int it = 0;
            while (r >= 32 - it) { r -= 32 - it; it++; }
            itile = it; jw = it + r;
        }
        float* sj = (float*)sbuf + g * 448;     // 64 boxes * 7 floats per group
        if (act) {
            int j = jw * 64 + l64;
            sj[l64 * 7 + 0] = g_lo[b][j][0];
            sj[l64 * 7 + 1] = g_lo[b][j][1];
            sj[l64 * 7 + 2] = g_lo[b][j][2];
            sj[l64 * 7 + 3] = g_hi[b][j][0];
            sj[l64 * 7 + 4] = g_hi[b][j][1];
            sj[l64 * 7 + 5] = g_hi[b][j][2];
            sj[l64 * 7 + 6] = g_vol[b][j];
        }
        __syncthreads();
        if (act) {
            int i = itile * 64 + l64;
            float lo0 = g_lo[b][i][0], lo1 = g_lo[b][i][1], lo2 = g_lo[b][i][2];
            float hi0 = g_hi[b][i][0], hi1 = g_hi[b][i][1], hi2 = g_hi[b][i][2];
            float voli = g_vol[b][i];
            int j0 = jw * 64;
            unsigned long long bits = 0ULL;
#pragma unroll 8
            for (int jj = 0; jj < 64; jj++) {
                int j = j0 + jj;
                const float* p = sj + jj * 7;
                float t0 = fmaxf(fminf(hi0, p[3]) - fmaxf(lo0, p[0]), 0.0f);
                float t1 = fmaxf(fminf(hi1, p[4]) - fmaxf(lo1, p[1]), 0.0f);
                float t2 = fmaxf(fminf(hi2, p[5]) - fmaxf(lo2, p[2]), 0.0f);
                float inter = t0 * t1 * t2;
                float uni = voli + p[6] - inter;
                float q = 0.25f * uni;              // exactly representable scale
                bool sup = false;
                if (inter > q) {
                    if (inter < q * 1.000001f) sup = (inter / uni > 0.25f);
                    else                       sup = true;
                }
                if (sup && (j > i)) bits |= (1ULL << jj);
            }
            g_mask[b][jw][i] = bits;
            if (bits) atomicOr(&g_nz[b][itile], 1ULL << l64);   // row i has a nonzero mask
        }
    }
    gsync();

    // ============ stage 7: nz-list greedy reduce (1 warp) + fused output ============
    if (bid < BATCH) {
        int b = bid;
        int* slist = (int*)sbuf;                              // up to 2048+CHUNK entries
        unsigned long long* skeep = (unsigned long long*)(sbuf + 16384);
        int* sL = (int*)(sbuf + 16384 + 256);
        if (t < 32) {
            unsigned long long nzw = __ldcg(&g_nz[b][t]);
            int cnt = __popcll(nzw);
            int pre = cnt;
            for (int d = 1; d < 32; d <<= 1) {
                int x = __shfl_up_sync(0xFFFFFFFFu, pre, d);
                if (t >= d) pre += x;
            }
            int off = pre - cnt;
            unsigned long long w = nzw;
            while (w) {
                int bit = __ffsll(w) - 1;
                w &= w - 1;
                slist[off++] = t * 64 + bit;
            }
            if (t == 31) {
                *sL = pre;
                int padded = (pre + CHUNK - 1) & ~(CHUNK - 1);
                for (int p = pre; p < padded; p++) slist[p] = -1;
            }
        }
        __syncthreads();
        int L = *sL;
        if (t < 32) {
            int lane = t;
            unsigned long long remv = 0ULL;
            for (int base = 0; base < L; base += CHUNK) {
                int rows[CHUNK];
                unsigned long long m[CHUNK];
#pragma unroll
                for (int q = 0; q < CHUNK; q++) {             // batched loads -> MLP
                    rows[q] = slist[base + q];
                    int rr = rows[q] < 0 ? 0 : rows[q];
                    // lower-triangle words of g_mask are never written; they are 0 by def
                    m[q] = (lane >= (rr >> 6)) ? g_mask[b][lane][rr] : 0ULL;
                }
#pragma unroll
                for (int q = 0; q < CHUNK; q++) {             // serial greedy chain
                    int row = rows[q];
                    if (row >= 0) {
                        int ws = row >> 6;
                        unsigned long long rw = __shfl_sync(0xFFFFFFFFu, remv, ws);
                        bool alive = !((rw >> (row & 63)) & 1ULL);
                        if (alive) remv |= m[q];
                    }
                }
            }
            skeep[lane] = ~remv;
        }
        __syncthreads();
        for (int row = t; row < TOPK; row += NTHR) {
            bool keep = (skeep[row >> 6] >> (row & 63)) & 1ULL;
            float* o = out + ((size_t)b * TOPK + row) * 7;
#pragma unroll
            for (int c = 0; c < 7; c++) o[c] = keep ? g_out7[b][row][c] : 0.0f;
        }
    }
}

extern "C" void kernel_launch(void* const* d_in, const int* in_sizes, int n_in,
                              void* d_out, int out_size) {
    const float* bboxes = (const float*)d_in[0];   // (2,6,64,96,96)
    const float* scores = (const float*)d_in[1];   // (2,64,96,96)
    float* out = (float*)d_out;                    // (2,2048,7)
    k_all<<<NBLK, NTHR>>>(bboxes, scores, out);
}